// round 8
// baseline (speedup 1.0000x reference)
#include <cuda_runtime.h>
#include <cuda_fp16.h>
#include <mma.h>
#include <math.h>
#include <stdint.h>

using namespace nvcuda;

// Problem constants
#define BB 8
#define TT 2048
#define DD 1024
#define EE 8
#define FF 4096
#define KK 2
#define NT (BB*TT)          // 16384 tokens
#define NROWS (NT*KK)       // 32768 token-expert assignments

// GEMM tiling (fp16 operands, fp32 accum)
#define BM 128
#define BN 256
#define BKT 64              // 64 halves = 128B per row per K tile
#define BKP 72              // padded K stride in halves
#define CN2 68              // padded fp32 staging stride for epilogue
#define NTHREADS 512
#define STAGE_BYTES ((BM+BN)*BKP*2)      // 55296 B (A tile + B tile)
#define NSTAGE 3
#define SMEM_BYTES (NSTAGE*STAGE_BYTES)  // 165888 B

// ---------------- device scratch (NEVER passed as kernel args from host) ----------------
__device__ int    g_cnt[EE];
__device__ int    g_fill[EE];
__device__ int    g_off[EE+1];
__device__ int    g_list[NROWS];
__device__ int    g_slot[NROWS];
__device__ unsigned char g_tope[NROWS];
__device__ float  g_topv[NROWS];
__device__ float  g_denom[BB*KK];
__device__ __half g_h[(size_t)NROWS*FF];    // 256 MB
__device__ float  g_y[(size_t)NROWS*DD];    // 128 MB
__device__ __half g_tokh[(size_t)NT*DD];    //  32 MB
__device__ __half g_w1h[(size_t)EE*FF*DD];  //  64 MB
__device__ __half g_w2h[(size_t)EE*DD*FF];  //  64 MB

// ---------------- helpers ----------------
__device__ __forceinline__ uint32_t s2u(const void* p) {
    uint32_t a;
    asm("{ .reg .u64 t; cvta.to.shared.u64 t, %1; cvt.u32.u64 %0, t; }" : "=r"(a) : "l"(p));
    return a;
}
__device__ __forceinline__ void cp16(uint32_t s, const void* g) {
    asm volatile("cp.async.cg.shared.global [%0], [%1], 16;" :: "r"(s), "l"(g));
}
__device__ __forceinline__ void cp_commit() {
    asm volatile("cp.async.commit_group;" ::: "memory");
}
template<int N>
__device__ __forceinline__ void cp_wait() {
    asm volatile("cp.async.wait_group %0;" :: "n"(N) : "memory");
}

// ---------------- prep: fp32 -> fp16 (dest selected INSIDE device code) ----------------
__global__ void f2h_k(const float* __restrict__ in, int which, int n4) {
    int i = blockIdx.x * blockDim.x + threadIdx.x;
    if (i >= n4) return;
    __half* out = (which == 0) ? g_tokh : (which == 1) ? g_w1h : g_w2h;
    float4 v = reinterpret_cast<const float4*>(in)[i];
    __half2 h01 = __floats2half2_rn(v.x, v.y);
    __half2 h23 = __floats2half2_rn(v.z, v.w);
    uint2 pk;
    pk.x = *reinterpret_cast<uint32_t*>(&h01);
    pk.y = *reinterpret_cast<uint32_t*>(&h23);
    reinterpret_cast<uint2*>(out)[i] = pk;
}

// ---------------- routing kernels (verbatim from passing kernel) ----------------
__global__ void zero_meta_k() {
    if (threadIdx.x < EE) { g_cnt[threadIdx.x] = 0; g_fill[threadIdx.x] = 0; }
}

__global__ void gate_topk_k(const float* __restrict__ tokens,
                            const float* __restrict__ gw,
                            const float* __restrict__ gb) {
    int warp = threadIdx.x >> 5, lane = threadIdx.x & 31;
    int t = blockIdx.x * 8 + warp;
    const float* x = tokens + (size_t)t * DD;
    float xr[32];
#pragma unroll
    for (int c = 0; c < 32; c++) xr[c] = x[c * 32 + lane];
    float best0 = -1e30f, best1 = -1e30f;
    int e0 = 0, e1 = 0;
#pragma unroll
    for (int e = 0; e < EE; e++) {
        const float* w = gw + e * DD;
        float acc = 0.f;
#pragma unroll
        for (int c = 0; c < 32; c++) acc += xr[c] * w[c * 32 + lane];
#pragma unroll
        for (int o = 16; o > 0; o >>= 1) acc += __shfl_xor_sync(0xffffffffu, acc, o);
        acc += gb[e];
        if (acc > best0) { best1 = best0; e1 = e0; best0 = acc; e0 = e; }
        else if (acc > best1) { best1 = acc; e1 = e; }
    }
    if (lane == 0) {
        g_tope[t * 2] = (unsigned char)e0;
        g_tope[t * 2 + 1] = (unsigned char)e1;
        g_topv[t * 2] = best0;
        g_topv[t * 2 + 1] = best1;
        atomicAdd(&g_cnt[e0], 1);
        atomicAdd(&g_cnt[e1], 1);
    }
}

__global__ void denom_k() {
    int b = blockIdx.x >> 1, k = blockIdx.x & 1;
    __shared__ float s[256];
    float a = 0.f;
    for (int i = 0; i < TT; i += 256) {
        int t = i + threadIdx.x;
        a += expf(g_topv[(size_t)(b * TT + t) * 2 + k]);
    }
    s[threadIdx.x] = a;
    __syncthreads();
    for (int o = 128; o > 0; o >>= 1) {
        if (threadIdx.x < o) s[threadIdx.x] += s[threadIdx.x + o];
        __syncthreads();
    }
    if (threadIdx.x == 0) g_denom[blockIdx.x] = s[0];
}

__global__ void scan_k() {
    int o = 0;
    for (int e = 0; e < EE; e++) { g_off[e] = o; o += g_cnt[e]; }
    g_off[EE] = o;
}

__global__ void fill_k() {
    int idx = blockIdx.x * blockDim.x + threadIdx.x;
    int e = g_tope[idx];
    int pos = g_off[e] + atomicAdd(&g_fill[e], 1);
    g_list[pos] = idx >> 1;
    g_slot[idx] = pos;
}

// ---------------- grouped GEMM: 128x256 tile, fp16 wmma, 3-stage cp.async ----------------
// GATHER=true : A = gathered g_tokh rows, B = g_w1h, out half -> g_h (relu), K=D, N=F
// GATHER=false: A = g_h contiguous,       B = g_w2h, out fp32 -> g_y,        K=F, N=D
template<bool GATHER>
__global__ void __launch_bounds__(NTHREADS) ffn_gemm(const float* __restrict__ bias,
                                                     int Kdim, int Ntot) {
    int e = blockIdx.z;
    int cnt_e = g_cnt[e];
    int mbase = blockIdx.x * BM;
    if (mbase >= cnt_e) return;
    int rowbase = g_off[e] + mbase;
    int nbase = blockIdx.y * BN;

    extern __shared__ __half smem[];
    uint32_t smem_u = s2u(smem);
    __shared__ const __half* arow[BM];

    int tid = threadIdx.x;
    if (tid < BM) {
        int r = (mbase + tid < cnt_e) ? tid : 0;   // clamp invalid rows
        int gr = rowbase + r;
        arow[tid] = GATHER ? (g_tokh + (size_t)g_list[gr] * Kdim)
                           : (g_h + (size_t)gr * Kdim);
    }
    __syncthreads();

    const __half* Bsrc = GATHER ? g_w1h : g_w2h;
    const __half* Bb = Bsrc + (size_t)e * Ntot * Kdim + (size_t)nbase * Kdim;

    wmma::fragment<wmma::accumulator, 16, 16, 16, float> acc[2][4];
#pragma unroll
    for (int i = 0; i < 2; i++)
#pragma unroll
        for (int j = 0; j < 4; j++) wmma::fill_fragment(acc[i][j], 0.f);

    int wid = tid >> 5;
    int wm = wid & 3;   // 4 warp-rows -> 32 rows each
    int wn = wid >> 2;  // 4 warp-cols -> 64 cols each (256 total)

    int ktiles = Kdim / BKT;

    auto issue = [&](int s, int k0) {
        uint32_t baseA = smem_u + (uint32_t)s * STAGE_BYTES;
        uint32_t baseB = baseA + (uint32_t)BM * BKP * 2;
        // A: 128 rows x 8 chunks (16B) = 1024 chunks
#pragma unroll
        for (int i = 0; i < 2; i++) {
            int f = tid + i * NTHREADS;
            int r = f >> 3, c = (f & 7) * 8;
            cp16(baseA + (uint32_t)(r * BKP + c) * 2, arow[r] + k0 + c);
        }
        // B: 256 rows x 8 chunks = 2048 chunks
#pragma unroll
        for (int i = 0; i < 4; i++) {
            int f = tid + i * NTHREADS;
            int r = f >> 3, c = (f & 7) * 8;
            cp16(baseB + (uint32_t)(r * BKP + c) * 2, Bb + (size_t)r * Kdim + k0 + c);
        }
        cp_commit();
    };

    issue(0, 0);
    issue(1, BKT);

    for (int kt = 0; kt < ktiles; kt++) {
        if (kt + 2 < ktiles) issue((kt + 2) % NSTAGE, (kt + 2) * BKT);
        else                 cp_commit();   // keep group count aligned
        cp_wait<2>();                        // stage kt ready
        __syncthreads();

        const __half* As = smem + (size_t)(kt % NSTAGE) * ((BM + BN) * BKP);
        const __half* Bs = As + BM * BKP;

#pragma unroll
        for (int kk = 0; kk < BKT; kk += 16) {
            wmma::fragment<wmma::matrix_a, 16, 16, 16, __half, wmma::row_major> af[2];
#pragma unroll
            for (int i = 0; i < 2; i++)
                wmma::load_matrix_sync(af[i], &As[(wm * 32 + i * 16) * BKP + kk], BKP);
#pragma unroll
            for (int j = 0; j < 4; j++) {
                wmma::fragment<wmma::matrix_b, 16, 16, 16, __half, wmma::col_major> bf;
                wmma::load_matrix_sync(bf, &Bs[(wn * 64 + j * 16) * BKP + kk], BKP);
#pragma unroll
                for (int i = 0; i < 2; i++)
                    wmma::mma_sync(acc[i][j], af[i], bf, acc[i][j]);
            }
        }
        __syncthreads();   // all warps done before this stage's buffer is reissued
    }

    // ---------------- epilogue: four 64-col passes staged in smem (fp32) ----------------
    float* Cs = reinterpret_cast<float*>(smem);   // 128 x CN2 fp32 = 34816 B
#pragma unroll
    for (int p = 0; p < 4; p++) {
        if (wn == p) {
#pragma unroll
            for (int i = 0; i < 2; i++)
#pragma unroll
                for (int j = 0; j < 4; j++)
                    wmma::store_matrix_sync(&Cs[(wm * 32 + i * 16) * CN2 + j * 16],
                                            acc[i][j], CN2, wmma::mem_row_major);
        }
        __syncthreads();
#pragma unroll
        for (int i = 0; i < 4; i++) {
            int f = tid + i * NTHREADS;     // [0,2048): 128 rows x 16 float4
            int r = f >> 4, c = (f & 15) * 4;
            if (mbase + r < cnt_e) {
                float4 v = *reinterpret_cast<float4*>(&Cs[r * CN2 + c]);
                int col = nbase + p * 64 + c;
                float4 bb = *reinterpret_cast<const float4*>(bias + (size_t)e * Ntot + col);
                v.x += bb.x; v.y += bb.y; v.z += bb.z; v.w += bb.w;
                if (GATHER) {
                    v.x = fmaxf(v.x, 0.f); v.y = fmaxf(v.y, 0.f);
                    v.z = fmaxf(v.z, 0.f); v.w = fmaxf(v.w, 0.f);
                    __half2 h01 = __floats2half2_rn(v.x, v.y);
                    __half2 h23 = __floats2half2_rn(v.z, v.w);
                    uint2 pk;
                    pk.x = *reinterpret_cast<uint32_t*>(&h01);
                    pk.y = *reinterpret_cast<uint32_t*>(&h23);
                    *reinterpret_cast<uint2*>(&g_h[(size_t)(rowbase + r) * Ntot + col]) = pk;
                } else {
                    *reinterpret_cast<float4*>(&g_y[(size_t)(rowbase + r) * Ntot + col]) = v;
                }
            }
        }
        __syncthreads();
    }
}

// out[t] = g0*y[slot0] + g1*y[slot1]
__global__ void combine_k(float* __restrict__ out) {
    int t = blockIdx.x;
    int b = t / TT;
    float g0 = expf(g_topv[2 * t])     / g_denom[b * 2 + 0];
    float g1 = expf(g_topv[2 * t + 1]) / g_denom[b * 2 + 1];
    const float4* y0 = reinterpret_cast<const float4*>(g_y + (size_t)g_slot[2 * t] * DD);
    const float4* y1 = reinterpret_cast<const float4*>(g_y + (size_t)g_slot[2 * t + 1] * DD);
    float4 a = y0[threadIdx.x];
    float4 c = y1[threadIdx.x];
    float4 r;
    r.x = g0 * a.x + g1 * c.x;
    r.y = g0 * a.y + g1 * c.y;
    r.z = g0 * a.z + g1 * c.z;
    r.w = g0 * a.w + g1 * c.w;
    reinterpret_cast<float4*>(out + (size_t)t * DD)[threadIdx.x] = r;
}

// ---------------- launch (only harness pointers + plain ints as args) ----------------
extern "C" void kernel_launch(void* const* d_in, const int* in_sizes, int n_in,
                              void* d_out, int out_size) {
    const float* tokens = (const float*)d_in[0];
    const float* gate_w = (const float*)d_in[1];
    const float* gate_b = (const float*)d_in[2];
    const float* w1     = (const float*)d_in[3];
    const float* b1     = (const float*)d_in[4];
    const float* w2     = (const float*)d_in[5];
    const float* b2     = (const float*)d_in[6];
    float* out = (float*)d_out;

    cudaFuncSetAttribute(ffn_gemm<true>,
                         cudaFuncAttributeMaxDynamicSharedMemorySize, SMEM_BYTES);
    cudaFuncSetAttribute(ffn_gemm<false>,
                         cudaFuncAttributeMaxDynamicSharedMemorySize, SMEM_BYTES);

    // fp32 -> fp16 operand conversion (dest chosen in device code)
    f2h_k<<<(NT * DD / 4 + 255) / 256, 256>>>(tokens, 0, NT * DD / 4);
    f2h_k<<<(EE * FF * DD / 4 + 255) / 256, 256>>>(w1, 1, EE * FF * DD / 4);
    f2h_k<<<(EE * DD * FF / 4 + 255) / 256, 256>>>(w2, 2, EE * DD * FF / 4);

    zero_meta_k<<<1, 32>>>();
    gate_topk_k<<<NT / 8, 256>>>(tokens, gate_w, gate_b);
    denom_k<<<BB * KK, 256>>>();
    scan_k<<<1, 1>>>();
    fill_k<<<NROWS / 256, 256>>>();

    // GEMM1: h = relu(X @ w1^T + b1)   K=D, N=F
    ffn_gemm<true><<<dim3(NROWS / BM, FF / BN, EE), NTHREADS, SMEM_BYTES>>>(b1, DD, FF);
    // GEMM2: y = h @ w2^T + b2         K=F, N=D
    ffn_gemm<false><<<dim3(NROWS / BM, DD / BN, EE), NTHREADS, SMEM_BYTES>>>(b2, FF, DD);

    combine_k<<<NT, 256>>>(out);
}

// round 9
// speedup vs baseline: 1.1326x; 1.1326x over previous
#include <cuda_runtime.h>
#include <cuda_fp16.h>
#include <mma.h>
#include <math.h>
#include <stdint.h>

using namespace nvcuda;

// Problem constants
#define BB 8
#define TT 2048
#define DD 1024
#define EE 8
#define FF 4096
#define KK 2
#define NT (BB*TT)          // 16384 tokens
#define NROWS (NT*KK)       // 32768 token-expert assignments

// GEMM tiling (fp16 operands, fp32 accum) — round-7 champion config
#define BM 128
#define BN 128
#define BKT 64              // 64 halves = 128B per row per tile
#define BKP 72              // padded K stride in halves
#define CN2 68              // padded fp32 staging stride for epilogue
#define TILE_BYTES (2*BM*BKP*2)        // A+B one stage = 36864 B
#define NSTAGE 2
#define SMEM_BYTES (NSTAGE*TILE_BYTES) // 73728 B -> 2 CTAs/SM

// ---------------- device scratch (NEVER passed as kernel args from host) ----------------
__device__ int    g_cnt[EE];
__device__ int    g_fill[EE];
__device__ int    g_off[EE+1];
__device__ int    g_list[NROWS];
__device__ int    g_slot[NROWS];
__device__ unsigned char g_tope[NROWS];
__device__ float  g_topv[NROWS];
__device__ float  g_denom[BB*KK];
__device__ __half g_h[(size_t)NROWS*FF];    // 256 MB
__device__ float  g_y[(size_t)NROWS*DD];    // 128 MB
__device__ __half g_tokh[(size_t)NT*DD];    //  32 MB
__device__ __half g_w1h[(size_t)EE*FF*DD];  //  64 MB
__device__ __half g_w2h[(size_t)EE*DD*FF];  //  64 MB

// ---------------- helpers ----------------
__device__ __forceinline__ uint32_t s2u(const void* p) {
    uint32_t a;
    asm("{ .reg .u64 t; cvta.to.shared.u64 t, %1; cvt.u32.u64 %0, t; }" : "=r"(a) : "l"(p));
    return a;
}
__device__ __forceinline__ void cp16(uint32_t s, const void* g) {
    asm volatile("cp.async.cg.shared.global [%0], [%1], 16;" :: "r"(s), "l"(g));
}
__device__ __forceinline__ void cp_commit() {
    asm volatile("cp.async.commit_group;" ::: "memory");
}
template<int N>
__device__ __forceinline__ void cp_wait() {
    asm volatile("cp.async.wait_group %0;" :: "n"(N) : "memory");
}

// ---------------- prep: fp32 -> fp16 (dest selected INSIDE device code) ----------------
__global__ void f2h_k(const float* __restrict__ in, int which, int n4) {
    int i = blockIdx.x * blockDim.x + threadIdx.x;
    if (i >= n4) return;
    __half* out = (which == 0) ? g_tokh : (which == 1) ? g_w1h : g_w2h;
    float4 v = reinterpret_cast<const float4*>(in)[i];
    __half2 h01 = __floats2half2_rn(v.x, v.y);
    __half2 h23 = __floats2half2_rn(v.z, v.w);
    uint2 pk;
    pk.x = *reinterpret_cast<uint32_t*>(&h01);
    pk.y = *reinterpret_cast<uint32_t*>(&h23);
    reinterpret_cast<uint2*>(out)[i] = pk;
}

// ---------------- routing kernels (verbatim from passing kernel) ----------------
__global__ void zero_meta_k() {
    if (threadIdx.x < EE) { g_cnt[threadIdx.x] = 0; g_fill[threadIdx.x] = 0; }
}

__global__ void gate_topk_k(const float* __restrict__ tokens,
                            const float* __restrict__ gw,
                            const float* __restrict__ gb) {
    int warp = threadIdx.x >> 5, lane = threadIdx.x & 31;
    int t = blockIdx.x * 8 + warp;
    const float* x = tokens + (size_t)t * DD;
    float xr[32];
#pragma unroll
    for (int c = 0; c < 32; c++) xr[c] = x[c * 32 + lane];
    float best0 = -1e30f, best1 = -1e30f;
    int e0 = 0, e1 = 0;
#pragma unroll
    for (int e = 0; e < EE; e++) {
        const float* w = gw + e * DD;
        float acc = 0.f;
#pragma unroll
        for (int c = 0; c < 32; c++) acc += xr[c] * w[c * 32 + lane];
#pragma unroll
        for (int o = 16; o > 0; o >>= 1) acc += __shfl_xor_sync(0xffffffffu, acc, o);
        acc += gb[e];
        if (acc > best0) { best1 = best0; e1 = e0; best0 = acc; e0 = e; }
        else if (acc > best1) { best1 = acc; e1 = e; }
    }
    if (lane == 0) {
        g_tope[t * 2] = (unsigned char)e0;
        g_tope[t * 2 + 1] = (unsigned char)e1;
        g_topv[t * 2] = best0;
        g_topv[t * 2 + 1] = best1;
        atomicAdd(&g_cnt[e0], 1);
        atomicAdd(&g_cnt[e1], 1);
    }
}

__global__ void denom_k() {
    int b = blockIdx.x >> 1, k = blockIdx.x & 1;
    __shared__ float s[256];
    float a = 0.f;
    for (int i = 0; i < TT; i += 256) {
        int t = i + threadIdx.x;
        a += expf(g_topv[(size_t)(b * TT + t) * 2 + k]);
    }
    s[threadIdx.x] = a;
    __syncthreads();
    for (int o = 128; o > 0; o >>= 1) {
        if (threadIdx.x < o) s[threadIdx.x] += s[threadIdx.x + o];
        __syncthreads();
    }
    if (threadIdx.x == 0) g_denom[blockIdx.x] = s[0];
}

__global__ void scan_k() {
    int o = 0;
    for (int e = 0; e < EE; e++) { g_off[e] = o; o += g_cnt[e]; }
    g_off[EE] = o;
}

__global__ void fill_k() {
    int idx = blockIdx.x * blockDim.x + threadIdx.x;
    int e = g_tope[idx];
    int pos = g_off[e] + atomicAdd(&g_fill[e], 1);
    g_list[pos] = idx >> 1;
    g_slot[idx] = pos;
}

// ---------------- grouped GEMM (fp16 wmma, fp32 accum, cp.async x2) ----------------
// GRID MAPPING: blockIdx.x = n-tile (fast), blockIdx.y = m-block, blockIdx.z = expert.
// Consecutive blocks share the same A rows -> A stays L2-resident instead of being
// re-streamed from DRAM once per n-tile.
template<bool GATHER>
__global__ void __launch_bounds__(256) ffn_gemm(const float* __restrict__ bias,
                                                int Kdim, int Ntot) {
    int e = blockIdx.z;
    int cnt_e = g_cnt[e];
    int mbase = blockIdx.y * BM;
    if (mbase >= cnt_e) return;
    int rowbase = g_off[e] + mbase;
    int nbase = blockIdx.x * BN;

    extern __shared__ __half smem[];
    uint32_t smem_u = s2u(smem);
    __shared__ const __half* arow[BM];

    int tid = threadIdx.x;
    if (tid < BM) {
        int r = (mbase + tid < cnt_e) ? tid : 0;   // clamp invalid rows
        int gr = rowbase + r;
        arow[tid] = GATHER ? (g_tokh + (size_t)g_list[gr] * Kdim)
                           : (g_h + (size_t)gr * Kdim);
    }
    __syncthreads();

    const __half* Bsrc = GATHER ? g_w1h : g_w2h;
    const __half* Bb = Bsrc + (size_t)e * Ntot * Kdim + (size_t)nbase * Kdim;

    wmma::fragment<wmma::accumulator, 16, 16, 16, float> acc[2][4];
#pragma unroll
    for (int i = 0; i < 2; i++)
#pragma unroll
        for (int j = 0; j < 4; j++) wmma::fill_fragment(acc[i][j], 0.f);

    int wid = tid >> 5;
    int wm = wid & 3;   // 4 warp-rows -> 32 rows each
    int wn = wid >> 2;  // 2 warp-cols -> 64 cols each

    int ktiles = Kdim / BKT;

    auto issue = [&](int s, int k0) {
        uint32_t base = smem_u + (uint32_t)s * TILE_BYTES;
#pragma unroll
        for (int i = 0; i < 4; i++) {
            int f = tid + i * 256;          // [0,1024): 128 rows x 8 chunks of 8 halves
            int r = f >> 3, c = (f & 7) * 8;
            uint32_t so = (uint32_t)(r * BKP + c) * 2;
            cp16(base + so, arow[r] + k0 + c);
            cp16(base + (uint32_t)BM * BKP * 2 + so, Bb + (size_t)r * Kdim + k0 + c);
        }
        cp_commit();
    };

    issue(0, 0);

    for (int kt = 0; kt < ktiles; kt++) {
        if (kt + 1 < ktiles) issue((kt + 1) & 1, (kt + 1) * BKT);
        else                 cp_commit();   // keep group count aligned
        cp_wait<1>();
        __syncthreads();

        const __half* As = smem + (size_t)(kt & 1) * (2 * BM * BKP);
        const __half* Bs = As + BM * BKP;

#pragma unroll
        for (int kk = 0; kk < BKT; kk += 16) {
            wmma::fragment<wmma::matrix_a, 16, 16, 16, __half, wmma::row_major> af[2];
#pragma unroll
            for (int i = 0; i < 2; i++)
                wmma::load_matrix_sync(af[i], &As[(wm * 32 + i * 16) * BKP + kk], BKP);
#pragma unroll
            for (int j = 0; j < 4; j++) {
                wmma::fragment<wmma::matrix_b, 16, 16, 16, __half, wmma::col_major> bf;
                wmma::load_matrix_sync(bf, &Bs[(wn * 64 + j * 16) * BKP + kk], BKP);
#pragma unroll
                for (int i = 0; i < 2; i++)
                    wmma::mma_sync(acc[i][j], af[i], bf, acc[i][j]);
            }
        }
        __syncthreads();   // all warps done with this stage before overwrite
    }

    // ---------------- epilogue: two 64-col halves staged in smem (fp32) ----------------
    float* Cs = reinterpret_cast<float*>(smem);   // 128 x CN2 fp32 = 34816 B < SMEM
#pragma unroll
    for (int p = 0; p < 2; p++) {
        if (wn == p) {
#pragma unroll
            for (int i = 0; i < 2; i++)
#pragma unroll
                for (int j = 0; j < 4; j++)
                    wmma::store_matrix_sync(&Cs[(wm * 32 + i * 16) * CN2 + j * 16],
                                            acc[i][j], CN2, wmma::mem_row_major);
        }
        __syncthreads();
#pragma unroll
        for (int i = 0; i < 8; i++) {
            int f = tid + i * 256;          // [0,2048): 128 rows x 16 float4
            int r = f >> 4, c = (f & 15) * 4;
            if (mbase + r < cnt_e) {
                float4 v = *reinterpret_cast<float4*>(&Cs[r * CN2 + c]);
                int col = nbase + p * 64 + c;
                float4 bb = *reinterpret_cast<const float4*>(bias + (size_t)e * Ntot + col);
                v.x += bb.x; v.y += bb.y; v.z += bb.z; v.w += bb.w;
                if (GATHER) {
                    v.x = fmaxf(v.x, 0.f); v.y = fmaxf(v.y, 0.f);
                    v.z = fmaxf(v.z, 0.f); v.w = fmaxf(v.w, 0.f);
                    __half2 h01 = __floats2half2_rn(v.x, v.y);
                    __half2 h23 = __floats2half2_rn(v.z, v.w);
                    uint2 pk;
                    pk.x = *reinterpret_cast<uint32_t*>(&h01);
                    pk.y = *reinterpret_cast<uint32_t*>(&h23);
                    *reinterpret_cast<uint2*>(&g_h[(size_t)(rowbase + r) * Ntot + col]) = pk;
                } else {
                    *reinterpret_cast<float4*>(&g_y[(size_t)(rowbase + r) * Ntot + col]) = v;
                }
            }
        }
        __syncthreads();
    }
}

// out[t] = g0*y[slot0] + g1*y[slot1]
__global__ void combine_k(float* __restrict__ out) {
    int t = blockIdx.x;
    int b = t / TT;
    float g0 = expf(g_topv[2 * t])     / g_denom[b * 2 + 0];
    float g1 = expf(g_topv[2 * t + 1]) / g_denom[b * 2 + 1];
    const float4* y0 = reinterpret_cast<const float4*>(g_y + (size_t)g_slot[2 * t] * DD);
    const float4* y1 = reinterpret_cast<const float4*>(g_y + (size_t)g_slot[2 * t + 1] * DD);
    float4 a = y0[threadIdx.x];
    float4 c = y1[threadIdx.x];
    float4 r;
    r.x = g0 * a.x + g1 * c.x;
    r.y = g0 * a.y + g1 * c.y;
    r.z = g0 * a.z + g1 * c.z;
    r.w = g0 * a.w + g1 * c.w;
    reinterpret_cast<float4*>(out + (size_t)t * DD)[threadIdx.x] = r;
}

// ---------------- launch (only harness pointers + plain ints as args) ----------------
extern "C" void kernel_launch(void* const* d_in, const int* in_sizes, int n_in,
                              void* d_out, int out_size) {
    const float* tokens = (const float*)d_in[0];
    const float* gate_w = (const float*)d_in[1];
    const float* gate_b = (const float*)d_in[2];
    const float* w1     = (const float*)d_in[3];
    const float* b1     = (const float*)d_in[4];
    const float* w2     = (const float*)d_in[5];
    const float* b2     = (const float*)d_in[6];
    float* out = (float*)d_out;

    cudaFuncSetAttribute(ffn_gemm<true>,
                         cudaFuncAttributeMaxDynamicSharedMemorySize, SMEM_BYTES);
    cudaFuncSetAttribute(ffn_gemm<false>,
                         cudaFuncAttributeMaxDynamicSharedMemorySize, SMEM_BYTES);

    // fp32 -> fp16 operand conversion (dest chosen in device code)
    f2h_k<<<(NT * DD / 4 + 255) / 256, 256>>>(tokens, 0, NT * DD / 4);
    f2h_k<<<(EE * FF * DD / 4 + 255) / 256, 256>>>(w1, 1, EE * FF * DD / 4);
    f2h_k<<<(EE * DD * FF / 4 + 255) / 256, 256>>>(w2, 2, EE * DD * FF / 4);

    zero_meta_k<<<1, 32>>>();
    gate_topk_k<<<NT / 8, 256>>>(tokens, gate_w, gate_b);
    denom_k<<<BB * KK, 256>>>();
    scan_k<<<1, 1>>>();
    fill_k<<<NROWS / 256, 256>>>();

    // GEMM1: h = relu(X @ w1^T + b1)   K=D, N=F   grid (n-tiles, m-blocks, E)
    ffn_gemm<true><<<dim3(FF / BN, NROWS / BM, EE), 256, SMEM_BYTES>>>(b1, DD, FF);
    // GEMM2: y = h @ w2^T + b2         K=F, N=D
    ffn_gemm<false><<<dim3(DD / BN, NROWS / BM, EE), 256, SMEM_BYTES>>>(b2, FF, DD);

    combine_k<<<NT, 256>>>(out);
}

// round 10
// speedup vs baseline: 1.1482x; 1.0138x over previous
#include <cuda_runtime.h>
#include <cuda_fp16.h>
#include <mma.h>
#include <math.h>
#include <stdint.h>

using namespace nvcuda;

// Problem constants
#define BB 8
#define TT 2048
#define DD 1024
#define EE 8
#define FF 4096
#define KK 2
#define NT (BB*TT)          // 16384 tokens
#define NROWS (NT*KK)       // 32768 token-expert assignments

// GEMM tiling (fp16 operands, fp32 accum)
#define BM 128
#define BN 128
#define BKT 64              // 64 halves = 128B per row per tile
#define BKP 72              // padded K stride in halves
#define CN2 68              // padded fp32 staging stride for epilogue
#define TILE_BYTES (2*BM*BKP*2)        // A+B one stage = 36864 B
#define NSTAGE 3
#define SMEM_BYTES (NSTAGE*TILE_BYTES) // 110592 B -> still 2 CTAs/SM (216KB/228KB)

// ---------------- device scratch (NEVER passed as kernel args from host) ----------------
__device__ int    g_cnt[EE];
__device__ int    g_fill[EE];
__device__ int    g_off[EE+1];
__device__ int    g_list[NROWS];
__device__ int    g_slot[NROWS];
__device__ unsigned char g_tope[NROWS];
__device__ float  g_topv[NROWS];
__device__ float  g_denom[BB*KK];
__device__ __half g_h[(size_t)NROWS*FF];    // 256 MB
__device__ float  g_y[(size_t)NROWS*DD];    // 128 MB
__device__ __half g_tokh[(size_t)NT*DD];    //  32 MB
__device__ __half g_w1h[(size_t)EE*FF*DD];  //  64 MB
__device__ __half g_w2h[(size_t)EE*DD*FF];  //  64 MB

// ---------------- helpers ----------------
__device__ __forceinline__ uint32_t s2u(const void* p) {
    uint32_t a;
    asm("{ .reg .u64 t; cvta.to.shared.u64 t, %1; cvt.u32.u64 %0, t; }" : "=r"(a) : "l"(p));
    return a;
}
__device__ __forceinline__ void cp16(uint32_t s, const void* g) {
    asm volatile("cp.async.cg.shared.global [%0], [%1], 16;" :: "r"(s), "l"(g));
}
__device__ __forceinline__ void cp_commit() {
    asm volatile("cp.async.commit_group;" ::: "memory");
}
template<int N>
__device__ __forceinline__ void cp_wait() {
    asm volatile("cp.async.wait_group %0;" :: "n"(N) : "memory");
}

// ---------------- prep: fp32 -> fp16 (dest selected INSIDE device code) ----------------
__global__ void f2h_k(const float* __restrict__ in, int which, int n4) {
    int i = blockIdx.x * blockDim.x + threadIdx.x;
    if (i >= n4) return;
    __half* out = (which == 0) ? g_tokh : (which == 1) ? g_w1h : g_w2h;
    float4 v = reinterpret_cast<const float4*>(in)[i];
    __half2 h01 = __floats2half2_rn(v.x, v.y);
    __half2 h23 = __floats2half2_rn(v.z, v.w);
    uint2 pk;
    pk.x = *reinterpret_cast<uint32_t*>(&h01);
    pk.y = *reinterpret_cast<uint32_t*>(&h23);
    reinterpret_cast<uint2*>(out)[i] = pk;
}

// ---------------- routing kernels (verbatim from passing kernel) ----------------
__global__ void zero_meta_k() {
    if (threadIdx.x < EE) { g_cnt[threadIdx.x] = 0; g_fill[threadIdx.x] = 0; }
}

__global__ void gate_topk_k(const float* __restrict__ tokens,
                            const float* __restrict__ gw,
                            const float* __restrict__ gb) {
    int warp = threadIdx.x >> 5, lane = threadIdx.x & 31;
    int t = blockIdx.x * 8 + warp;
    const float* x = tokens + (size_t)t * DD;
    float xr[32];
#pragma unroll
    for (int c = 0; c < 32; c++) xr[c] = x[c * 32 + lane];
    float best0 = -1e30f, best1 = -1e30f;
    int e0 = 0, e1 = 0;
#pragma unroll
    for (int e = 0; e < EE; e++) {
        const float* w = gw + e * DD;
        float acc = 0.f;
#pragma unroll
        for (int c = 0; c < 32; c++) acc += xr[c] * w[c * 32 + lane];
#pragma unroll
        for (int o = 16; o > 0; o >>= 1) acc += __shfl_xor_sync(0xffffffffu, acc, o);
        acc += gb[e];
        if (acc > best0) { best1 = best0; e1 = e0; best0 = acc; e0 = e; }
        else if (acc > best1) { best1 = acc; e1 = e; }
    }
    if (lane == 0) {
        g_tope[t * 2] = (unsigned char)e0;
        g_tope[t * 2 + 1] = (unsigned char)e1;
        g_topv[t * 2] = best0;
        g_topv[t * 2 + 1] = best1;
        atomicAdd(&g_cnt[e0], 1);
        atomicAdd(&g_cnt[e1], 1);
    }
}

__global__ void denom_k() {
    int b = blockIdx.x >> 1, k = blockIdx.x & 1;
    __shared__ float s[256];
    float a = 0.f;
    for (int i = 0; i < TT; i += 256) {
        int t = i + threadIdx.x;
        a += expf(g_topv[(size_t)(b * TT + t) * 2 + k]);
    }
    s[threadIdx.x] = a;
    __syncthreads();
    for (int o = 128; o > 0; o >>= 1) {
        if (threadIdx.x < o) s[threadIdx.x] += s[threadIdx.x + o];
        __syncthreads();
    }
    if (threadIdx.x == 0) g_denom[blockIdx.x] = s[0];
}

__global__ void scan_k() {
    int o = 0;
    for (int e = 0; e < EE; e++) { g_off[e] = o; o += g_cnt[e]; }
    g_off[EE] = o;
}

__global__ void fill_k() {
    int idx = blockIdx.x * blockDim.x + threadIdx.x;
    int e = g_tope[idx];
    int pos = g_off[e] + atomicAdd(&g_fill[e], 1);
    g_list[pos] = idx >> 1;
    g_slot[idx] = pos;
}

// ---------------- grouped GEMM: fp16 wmma, 3-stage cp.async, ONE sync per K-tile ----------------
// CUTLASS multistage pattern: the barrier publishing tile kt also proves all warps
// finished tile kt-1, which is the hazard condition for overwriting stage (kt-1)%3.
template<bool GATHER>
__global__ void __launch_bounds__(256) ffn_gemm(const float* __restrict__ bias,
                                                int Kdim, int Ntot) {
    int e = blockIdx.z;
    int cnt_e = g_cnt[e];
    int mbase = blockIdx.y * BM;
    if (mbase >= cnt_e) return;
    int rowbase = g_off[e] + mbase;
    int nbase = blockIdx.x * BN;

    extern __shared__ __half smem[];
    uint32_t smem_u = s2u(smem);
    __shared__ const __half* arow[BM];

    int tid = threadIdx.x;
    if (tid < BM) {
        int r = (mbase + tid < cnt_e) ? tid : 0;   // clamp invalid rows
        int gr = rowbase + r;
        arow[tid] = GATHER ? (g_tokh + (size_t)g_list[gr] * Kdim)
                           : (g_h + (size_t)gr * Kdim);
    }
    __syncthreads();

    const __half* Bsrc = GATHER ? g_w1h : g_w2h;
    const __half* Bb = Bsrc + (size_t)e * Ntot * Kdim + (size_t)nbase * Kdim;

    wmma::fragment<wmma::accumulator, 16, 16, 16, float> acc[2][4];
#pragma unroll
    for (int i = 0; i < 2; i++)
#pragma unroll
        for (int j = 0; j < 4; j++) wmma::fill_fragment(acc[i][j], 0.f);

    int wid = tid >> 5;
    int wm = wid & 3;   // 4 warp-rows -> 32 rows each
    int wn = wid >> 2;  // 2 warp-cols -> 64 cols each

    int ktiles = Kdim / BKT;

    auto issue = [&](int s, int k0) {
        uint32_t base = smem_u + (uint32_t)s * TILE_BYTES;
#pragma unroll
        for (int i = 0; i < 4; i++) {
            int f = tid + i * 256;          // [0,1024): 128 rows x 8 chunks of 8 halves
            int r = f >> 3, c = (f & 7) * 8;
            uint32_t so = (uint32_t)(r * BKP + c) * 2;
            cp16(base + so, arow[r] + k0 + c);
            cp16(base + (uint32_t)BM * BKP * 2 + so, Bb + (size_t)r * Kdim + k0 + c);
        }
        cp_commit();
    };

    // prologue: NSTAGE-1 stages in flight
    issue(0, 0);
    issue(1, BKT);

    for (int kt = 0; kt < ktiles; kt++) {
        cp_wait<NSTAGE - 2>();   // tile kt arrived (commits before this = kt+2)
        __syncthreads();         // publish tile kt; also: all warps done with tile kt-1
        if (kt + 2 < ktiles) issue((kt + 2) % NSTAGE, (kt + 2) * BKT);
        else                 cp_commit();   // keep group accounting aligned

        const __half* As = smem + (size_t)((kt % NSTAGE)) * (2 * BM * BKP);
        const __half* Bs = As + BM * BKP;

#pragma unroll
        for (int kk = 0; kk < BKT; kk += 16) {
            wmma::fragment<wmma::matrix_a, 16, 16, 16, __half, wmma::row_major> af[2];
#pragma unroll
            for (int i = 0; i < 2; i++)
                wmma::load_matrix_sync(af[i], &As[(wm * 32 + i * 16) * BKP + kk], BKP);
#pragma unroll
            for (int j = 0; j < 4; j++) {
                wmma::fragment<wmma::matrix_b, 16, 16, 16, __half, wmma::col_major> bf;
                wmma::load_matrix_sync(bf, &Bs[(wn * 64 + j * 16) * BKP + kk], BKP);
#pragma unroll
                for (int i = 0; i < 2; i++)
                    wmma::mma_sync(acc[i][j], af[i], bf, acc[i][j]);
            }
        }
        // no tail sync: next iteration's barrier provides the ordering
    }
    __syncthreads();   // protect epilogue smem reuse against last-tile readers

    // ---------------- epilogue: two 64-col halves staged in smem (fp32) ----------------
    float* Cs = reinterpret_cast<float*>(smem);   // 128 x CN2 fp32 = 34816 B < SMEM
#pragma unroll
    for (int p = 0; p < 2; p++) {
        if (wn == p) {
#pragma unroll
            for (int i = 0; i < 2; i++)
#pragma unroll
                for (int j = 0; j < 4; j++)
                    wmma::store_matrix_sync(&Cs[(wm * 32 + i * 16) * CN2 + j * 16],
                                            acc[i][j], CN2, wmma::mem_row_major);
        }
        __syncthreads();
#pragma unroll
        for (int i = 0; i < 8; i++) {
            int f = tid + i * 256;          // [0,2048): 128 rows x 16 float4
            int r = f >> 4, c = (f & 15) * 4;
            if (mbase + r < cnt_e) {
                float4 v = *reinterpret_cast<float4*>(&Cs[r * CN2 + c]);
                int col = nbase + p * 64 + c;
                float4 bb = *reinterpret_cast<const float4*>(bias + (size_t)e * Ntot + col);
                v.x += bb.x; v.y += bb.y; v.z += bb.z; v.w += bb.w;
                if (GATHER) {
                    v.x = fmaxf(v.x, 0.f); v.y = fmaxf(v.y, 0.f);
                    v.z = fmaxf(v.z, 0.f); v.w = fmaxf(v.w, 0.f);
                    __half2 h01 = __floats2half2_rn(v.x, v.y);
                    __half2 h23 = __floats2half2_rn(v.z, v.w);
                    uint2 pk;
                    pk.x = *reinterpret_cast<uint32_t*>(&h01);
                    pk.y = *reinterpret_cast<uint32_t*>(&h23);
                    *reinterpret_cast<uint2*>(&g_h[(size_t)(rowbase + r) * Ntot + col]) = pk;
                } else {
                    *reinterpret_cast<float4*>(&g_y[(size_t)(rowbase + r) * Ntot + col]) = v;
                }
            }
        }
        __syncthreads();
    }
}

// out[t] = g0*y[slot0] + g1*y[slot1]
__global__ void combine_k(float* __restrict__ out) {
    int t = blockIdx.x;
    int b = t / TT;
    float g0 = expf(g_topv[2 * t])     / g_denom[b * 2 + 0];
    float g1 = expf(g_topv[2 * t + 1]) / g_denom[b * 2 + 1];
    const float4* y0 = reinterpret_cast<const float4*>(g_y + (size_t)g_slot[2 * t] * DD);
    const float4* y1 = reinterpret_cast<const float4*>(g_y + (size_t)g_slot[2 * t + 1] * DD);
    float4 a = y0[threadIdx.x];
    float4 c = y1[threadIdx.x];
    float4 r;
    r.x = g0 * a.x + g1 * c.x;
    r.y = g0 * a.y + g1 * c.y;
    r.z = g0 * a.z + g1 * c.z;
    r.w = g0 * a.w + g1 * c.w;
    reinterpret_cast<float4*>(out + (size_t)t * DD)[threadIdx.x] = r;
}

// ---------------- launch (only harness pointers + plain ints as args) ----------------
extern "C" void kernel_launch(void* const* d_in, const int* in_sizes, int n_in,
                              void* d_out, int out_size) {
    const float* tokens = (const float*)d_in[0];
    const float* gate_w = (const float*)d_in[1];
    const float* gate_b = (const float*)d_in[2];
    const float* w1     = (const float*)d_in[3];
    const float* b1     = (const float*)d_in[4];
    const float* w2     = (const float*)d_in[5];
    const float* b2     = (const float*)d_in[6];
    float* out = (float*)d_out;

    cudaFuncSetAttribute(ffn_gemm<true>,
                         cudaFuncAttributeMaxDynamicSharedMemorySize, SMEM_BYTES);
    cudaFuncSetAttribute(ffn_gemm<false>,
                         cudaFuncAttributeMaxDynamicSharedMemorySize, SMEM_BYTES);

    // fp32 -> fp16 operand conversion (dest chosen in device code)
    f2h_k<<<(NT * DD / 4 + 255) / 256, 256>>>(tokens, 0, NT * DD / 4);
    f2h_k<<<(EE * FF * DD / 4 + 255) / 256, 256>>>(w1, 1, EE * FF * DD / 4);
    f2h_k<<<(EE * DD * FF / 4 + 255) / 256, 256>>>(w2, 2, EE * DD * FF / 4);

    zero_meta_k<<<1, 32>>>();
    gate_topk_k<<<NT / 8, 256>>>(tokens, gate_w, gate_b);
    denom_k<<<BB * KK, 256>>>();
    scan_k<<<1, 1>>>();
    fill_k<<<NROWS / 256, 256>>>();

    // GEMM1: h = relu(X @ w1^T + b1)   K=D, N=F   grid (n-tiles, m-blocks, E)
    ffn_gemm<true><<<dim3(FF / BN, NROWS / BM, EE), 256, SMEM_BYTES>>>(b1, DD, FF);
    // GEMM2: y = h @ w2^T + b2         K=F, N=D
    ffn_gemm<false><<<dim3(DD / BN, NROWS / BM, EE), 256, SMEM_BYTES>>>(b2, FF, DD);

    combine_k<<<NT, 256>>>(out);
}